// round 11
// baseline (speedup 1.0000x reference)
#include <cuda_runtime.h>

// ThoughtEngine: B=8, L=1024, D=1024, H=16, HD=64, S=32, C=8. fp32.
// R11: champion R10 + persistent 256-block loop kernel (grid ticket barrier),
// vectorized __ldcg on mutable buffers, register-carried LN residuals.

#define LL (size_t)

static const size_t OFF_QKVH = 0;                              // 8192*3072
static const size_t OFF_BUF  = OFF_QKVH + LL 8192 * 3072;      // 8*32*1024
static const size_t OFF_KVB  = OFF_BUF  + LL 8 * 32 * 1024;    // 8*32*2048
static const size_t OFF_CTX  = OFF_KVB  + LL 8 * 32 * 2048;
static const size_t OFF_TOK  = OFF_CTX + 8192;
static const size_t OFF_TMP  = OFF_TOK + 8192;
static const size_t OFF_TMP2 = OFF_TMP + 8192;
static const size_t OFF_H1   = OFF_TMP2 + 8192;                // 8*2048
static const size_t OFF_Q    = OFF_H1 + 16384;
static const size_t OFF_AO   = OFF_Q + 8192;
static const size_t OFF_KVS  = OFF_AO + 8192;                  // 64*2048
static const size_t OFF_SSUM = OFF_KVS + 131072;               // 64*1024
static const size_t OFF_O    = OFF_SSUM + 65536;               // 8192*1024
static const size_t OFF_ATT  = OFF_O + LL 8192 * 1024;         // 8192*1024
static const size_t SCR_TOT  = OFF_ATT + LL 8192 * 1024;

__device__ __align__(16) float g_scratch[SCR_TOT];
__device__ unsigned g_bar = 0;   // monotonic ticket; 2^32 % 256 == 0 -> wrap-safe

__device__ __forceinline__ float geluf(float x) {
    return 0.5f * x * (1.0f + erff(x * 0.7071067811865475f));
}

// Grid barrier over exactly 256 resident blocks (proven pattern from R6 @128).
__device__ __forceinline__ void gsync() {
    __syncthreads();
    if (threadIdx.x == 0) {
        __threadfence();
        unsigned t = atomicAdd(&g_bar, 1u);
        unsigned target = (t & ~255u) + 256u;
        while ((int)(*(volatile unsigned*)&g_bar - target) < 0) { }
        __threadfence();
    }
    __syncthreads();
}

// In-place LayerNorm of 8 rows x 1024 staged in smem. blockDim == 256.
__device__ __forceinline__ void ln_inplace(float* sA, const float* g,
                                           const float* bv, float* st) {
    int tid = threadIdx.x, lane = tid & 31, w = tid >> 5;   // 8 warps = 8 rows
    float s = 0.f;
    #pragma unroll
    for (int c = lane; c < 1024; c += 32) s += sA[w * 1024 + c];
    #pragma unroll
    for (int o = 16; o; o >>= 1) s += __shfl_xor_sync(0xffffffffu, s, o);
    float mean = s * (1.0f / 1024.0f);
    float v = 0.f;
    #pragma unroll
    for (int c = lane; c < 1024; c += 32) { float d = sA[w * 1024 + c] - mean; v += d * d; }
    #pragma unroll
    for (int o = 16; o; o >>= 1) v += __shfl_xor_sync(0xffffffffu, v, o);
    if (lane == 0) { st[w] = mean; st[8 + w] = rsqrtf(v * (1.0f / 1024.0f) + 1e-5f); }
    __syncthreads();
    for (int idx = tid; idx < 8192; idx += 256) {
        int r = idx >> 10, d = idx & 1023;
        sA[idx] = (sA[idx] - st[r]) * st[8 + r] * g[d] + bv[d];
    }
    __syncthreads();
}

// ctx[b,d] = mean_l hidden[b,l,d]
__global__ void mean_kernel(const float* __restrict__ hidden, float* __restrict__ ctx) {
    int b = blockIdx.y;
    int d = blockIdx.x * 256 + threadIdx.x;
    const float* p = hidden + LL b * 1048576 + d;
    float s = 0.f;
    #pragma unroll 8
    for (int l = 0; l < 1024; ++l) s += p[LL l * 1024];
    ctx[b * 1024 + d] = s * (1.0f / 1024.0f);
}

__global__ void copy_to_buf(const float* __restrict__ tok, float* __restrict__ buf, int slot) {
    int b = blockIdx.x;
    int d = blockIdx.y * 256 + threadIdx.x;
    buf[LL(b * 32 + slot) * 1024 + d] = tok[b * 1024 + d];
}

// Scalar GEMM (proven): C[M,N] = A[M,K]@B[N,K]^T + bias. BM=128 BN=64 BK=16.
__global__ __launch_bounds__(256) void sgemm(
    const float* __restrict__ A, const float* __restrict__ B,
    const float* __restrict__ bias, float* __restrict__ C,
    int M, int N, int K)
{
    __shared__ __align__(16) float As[16][128];
    __shared__ __align__(16) float Bs[16][64];
    int tid = threadIdx.x;
    int tx = tid & 15, ty = tid >> 4;
    int bm = blockIdx.y * 128, bn = blockIdx.x * 64;
    float acc[8][4];
    #pragma unroll
    for (int i = 0; i < 8; ++i)
        #pragma unroll
        for (int j = 0; j < 4; ++j) acc[i][j] = 0.f;

    for (int kk = 0; kk < K; kk += 16) {
        #pragma unroll
        for (int s = tid; s < 512; s += 256) {
            int r = s >> 2, c = (s & 3) << 2;
            int gr = bm + r;
            float4 v = make_float4(0.f, 0.f, 0.f, 0.f);
            if (gr < M) v = *reinterpret_cast<const float4*>(A + LL gr * K + kk + c);
            As[c][r] = v.x; As[c + 1][r] = v.y; As[c + 2][r] = v.z; As[c + 3][r] = v.w;
        }
        {
            int r = tid >> 2, c = (tid & 3) << 2;
            float4 v = *reinterpret_cast<const float4*>(B + LL(bn + r) * K + kk + c);
            Bs[c][r] = v.x; Bs[c + 1][r] = v.y; Bs[c + 2][r] = v.z; Bs[c + 3][r] = v.w;
        }
        __syncthreads();
        #pragma unroll
        for (int k = 0; k < 16; ++k) {
            float a[8], bb[4];
            #pragma unroll
            for (int i = 0; i < 8; ++i) a[i] = As[k][ty * 8 + i];
            #pragma unroll
            for (int j = 0; j < 4; ++j) bb[j] = Bs[k][tx * 4 + j];
            #pragma unroll
            for (int i = 0; i < 8; ++i)
                #pragma unroll
                for (int j = 0; j < 4; ++j) acc[i][j] += a[i] * bb[j];
        }
        __syncthreads();
    }
    #pragma unroll
    for (int i = 0; i < 8; ++i) {
        int row = bm + ty * 8 + i;
        if (row < M) {
            float* cr = C + LL row * N + bn + tx * 4;
            #pragma unroll
            for (int j = 0; j < 4; ++j) cr[j] = acc[i][j] + bias[bn + tx * 4 + j];
        }
    }
}

// out[b,n] = A[b,:K].W[n,:K] + bias[n], 8 rows, warp per n (Phase A tok0 only).
__global__ __launch_bounds__(256) void smallgemm8(
    const float* __restrict__ A, int K,
    const float* __restrict__ W, const float* __restrict__ bias,
    float* __restrict__ out, int N)
{
    __shared__ __align__(16) float As[8192];
    int tid = threadIdx.x, lane = tid & 31, w = tid >> 5;
    int n = blockIdx.x * 8 + w;
    float acc[8];
    #pragma unroll
    for (int b = 0; b < 8; ++b) acc[b] = 0.f;
    for (int kk = 0; kk < K; kk += 1024) {
        for (int i = tid; i < 8192; i += 256) {
            int b = i >> 10, k = i & 1023;
            As[i] = A[LL b * K + kk + k];
        }
        __syncthreads();
        const float4* wr = reinterpret_cast<const float4*>(W + LL n * K + kk);
        for (int k4 = lane; k4 < 256; k4 += 32) {
            float4 wv = wr[k4];
            #pragma unroll
            for (int b = 0; b < 8; ++b) {
                float4 av = reinterpret_cast<const float4*>(As + b * 1024)[k4];
                acc[b] += wv.x * av.x + wv.y * av.y + wv.z * av.z + wv.w * av.w;
            }
        }
        __syncthreads();
    }
    #pragma unroll
    for (int off = 16; off; off >>= 1)
        #pragma unroll
        for (int b = 0; b < 8; ++b) acc[b] += __shfl_down_sync(0xffffffffu, acc[b], off);
    if (lane == 0) {
        float bv = bias[n];
        #pragma unroll
        for (int b = 0; b < 8; ++b) out[b * N + n] = acc[b] + bv;
    }
}

// ============================================================================
// Persistent loop kernel: 256 blocks x 256 threads, all co-resident
// (__launch_bounds__(256,2): 148 SMs x 2 = 296 slots >= 256).
// Cross-barrier-mutable buffers (tmp2,q,kvb,ao,tmp,h1) read ONLY via __ldcg
// (vectorized). Weights/qkvh are read-only within the kernel: normal loads,
// L1-cached across steps (bid->n map is step-invariant).
// ============================================================================
__global__ __launch_bounds__(256, 2) void loop_kernel(
    const float* __restrict__ aiw, const float* __restrict__ aib,
    const float* __restrict__ aow, const float* __restrict__ aob,
    const float* __restrict__ fw1, const float* __restrict__ fb1,
    const float* __restrict__ fw2, const float* __restrict__ fb2,
    const float* __restrict__ ln1g, const float* __restrict__ ln1b,
    const float* __restrict__ ln2g, const float* __restrict__ ln2b,
    const float* __restrict__ qkvh, const float* __restrict__ tok0,
    float* q, float* kvb, float* ao, float* tmp, float* h1, float* tmp2,
    float* buf)
{
    __shared__ __align__(16) float sA[8192];
    __shared__ float st[16];
    __shared__ float sc[1056];
    __shared__ float red[256];
    __shared__ float part[8][64];
    int tid = threadIdx.x, lane = tid & 31, w = tid >> 5;
    int bid = blockIdx.x;

    for (int i = 1; i < 32; ++i) {
        // ---- S1: (LN2 for i>=2) + qkv -> q (n<1024), kvb slot i-1 ----
        if (i == 1) {
            for (int idx = tid; idx < 8192; idx += 256) sA[idx] = tok0[idx];
            __syncthreads();
        } else {
            const float4* src4 = reinterpret_cast<const float4*>(tmp2);
            for (int idx = tid; idx < 2048; idx += 256) {
                float4 v = __ldcg(src4 + idx);
                reinterpret_cast<float4*>(sA)[idx] = v;
            }
            __syncthreads();
            ln_inplace(sA, ln2g, ln2b, st);
            if (bid == 0) {
                for (int idx = tid; idx < 8192; idx += 256) {
                    int b = idx >> 10, d = idx & 1023;
                    buf[LL(b * 32 + i - 1) * 1024 + d] = sA[idx];
                }
            }
        }
        // register-carried LN2 residual for S3 (n0 = bid*8+w, uniform per warp)
        int n0 = bid * 8 + w;
        float tokres[8];
        #pragma unroll
        for (int b = 0; b < 8; ++b) tokres[b] = sA[b * 1024 + n0];

        for (int n = n0; n < 3072; n += 2048) {
            const float4* wr = reinterpret_cast<const float4*>(aiw + LL n * 1024);
            float acc[8];
            #pragma unroll
            for (int b = 0; b < 8; ++b) acc[b] = 0.f;
            for (int k4 = lane; k4 < 256; k4 += 32) {
                float4 wv = wr[k4];
                #pragma unroll
                for (int b = 0; b < 8; ++b) {
                    float4 av = reinterpret_cast<const float4*>(sA + b * 1024)[k4];
                    acc[b] += wv.x * av.x + wv.y * av.y + wv.z * av.z + wv.w * av.w;
                }
            }
            #pragma unroll
            for (int off = 16; off; off >>= 1)
                #pragma unroll
                for (int b = 0; b < 8; ++b) acc[b] += __shfl_down_sync(0xffffffffu, acc[b], off);
            if (lane == 0) {
                float bv = aib[n];
                #pragma unroll
                for (int b = 0; b < 8; ++b) {
                    float v = acc[b] + bv;
                    if (n < 1024) q[b * 1024 + n] = v;
                    else kvb[LL(b * 32 + i - 1) * 2048 + (n - 1024)] = v;
                }
            }
        }
        gsync();

        // ---- S2: attention over Lk = 1024 + i keys; blocks 0..127 = (b,h) ----
        if (bid < 128) {
            int b = bid >> 4, h = bid & 15;
            int Lk = 1024 + i;
            if (tid < 64) sA[tid] = __ldcg(q + b * 1024 + h * 64 + tid);
            __syncthreads();
            float lmax = -1e30f;
            for (int j = tid; j < Lk; j += 256) {
                float s = 0.f;
                const float4* q4 = reinterpret_cast<const float4*>(sA);
                if (j < 1024) {
                    const float4* k4 = reinterpret_cast<const float4*>(
                        qkvh + LL(b * 1024 + j) * 3072 + 1024 + h * 64);
                    #pragma unroll
                    for (int d = 0; d < 16; ++d) {
                        float4 kv = k4[d], qv = q4[d];
                        s += kv.x * qv.x + kv.y * qv.y + kv.z * qv.z + kv.w * qv.w;
                    }
                } else {
                    const float4* k4 = reinterpret_cast<const float4*>(
                        kvb + LL(b * 32 + j - 1024) * 2048 + h * 64);
                    #pragma unroll
                    for (int d = 0; d < 16; ++d) {
                        float4 kv = __ldcg(k4 + d);
                        float4 qv = q4[d];
                        s += kv.x * qv.x + kv.y * qv.y + kv.z * qv.z + kv.w * qv.w;
                    }
                }
                s *= 0.125f;
                sc[j] = s;
                lmax = fmaxf(lmax, s);
            }
            red[tid] = lmax; __syncthreads();
            for (int o = 128; o; o >>= 1) { if (tid < o) red[tid] = fmaxf(red[tid], red[tid + o]); __syncthreads(); }
            float m = red[0];
            __syncthreads();
            float lsum = 0.f;
            for (int j = tid; j < Lk; j += 256) { float p = __expf(sc[j] - m); sc[j] = p; lsum += p; }
            red[tid] = lsum; __syncthreads();
            for (int o = 128; o; o >>= 1) { if (tid < o) red[tid] += red[tid + o]; __syncthreads(); }
            float inv = 1.0f / red[0];

            int g = tid >> 5, d0 = (tid & 31) * 2;
            float ax = 0.f, ay = 0.f;
            for (int j = g; j < Lk; j += 8) {
                float2 v;
                if (j < 1024)
                    v = *reinterpret_cast<const float2*>(
                        qkvh + LL(b * 1024 + j) * 3072 + 2048 + h * 64 + d0);
                else
                    v = __ldcg(reinterpret_cast<const float2*>(
                        kvb + LL(b * 32 + j - 1024) * 2048 + 1024 + h * 64 + d0));
                float p = sc[j];
                ax += p * v.x; ay += p * v.y;
            }
            part[g][d0] = ax; part[g][d0 + 1] = ay;
            __syncthreads();
            if (tid < 64) {
                float s = 0.f;
                #pragma unroll
                for (int gg = 0; gg < 8; ++gg) s += part[gg][tid];
                ao[b * 1024 + h * 64 + tid] = s * inv;
            }
        }
        gsync();

        // ---- S3: out-proj + residual -> tmp (blocks 0..127) ----
        if (bid < 128) {
            const float4* src4 = reinterpret_cast<const float4*>(ao);
            for (int idx = tid; idx < 2048; idx += 256)
                reinterpret_cast<float4*>(sA)[idx] = __ldcg(src4 + idx);
            __syncthreads();
            int n = n0;   // < 1024
            const float4* wr = reinterpret_cast<const float4*>(aow + LL n * 1024);
            float acc[8];
            #pragma unroll
            for (int b = 0; b < 8; ++b) acc[b] = 0.f;
            for (int k4 = lane; k4 < 256; k4 += 32) {
                float4 wv = wr[k4];
                #pragma unroll
                for (int b = 0; b < 8; ++b) {
                    float4 av = reinterpret_cast<const float4*>(sA + b * 1024)[k4];
                    acc[b] += wv.x * av.x + wv.y * av.y + wv.z * av.z + wv.w * av.w;
                }
            }
            #pragma unroll
            for (int off = 16; off; off >>= 1)
                #pragma unroll
                for (int b = 0; b < 8; ++b) acc[b] += __shfl_down_sync(0xffffffffu, acc[b], off);
            if (lane == 0) {
                float bv = aob[n];
                #pragma unroll
                for (int b = 0; b < 8; ++b)
                    tmp[b * 1024 + n] = acc[b] + bv + tokres[b];
            }
        }
        gsync();

        // ---- S4: LN1 + FFN1(gelu) -> h1 (all 256 blocks; n = n0 < 2048) ----
        {
            const float4* src4 = reinterpret_cast<const float4*>(tmp);
            for (int idx = tid; idx < 2048; idx += 256)
                reinterpret_cast<float4*>(sA)[idx] = __ldcg(src4 + idx);
            __syncthreads();
            ln_inplace(sA, ln1g, ln1b, st);
        }
        // register-carried LN1 residual for S5 (only valid/used when bid<128)
        float resv[8];
        #pragma unroll
        for (int b = 0; b < 8; ++b) resv[b] = sA[b * 1024 + (n0 & 1023)];
        {
            int n = n0;   // < 2048, exactly one per warp
            const float4* wr = reinterpret_cast<const float4*>(fw1 + LL n * 1024);
            float acc[8];
            #pragma unroll
            for (int b = 0; b < 8; ++b) acc[b] = 0.f;
            for (int k4 = lane; k4 < 256; k4 += 32) {
                float4 wv = wr[k4];
                #pragma unroll
                for (int b = 0; b < 8; ++b) {
                    float4 av = reinterpret_cast<const float4*>(sA + b * 1024)[k4];
                    acc[b] += wv.x * av.x + wv.y * av.y + wv.z * av.z + wv.w * av.w;
                }
            }
            #pragma unroll
            for (int off = 16; off; off >>= 1)
                #pragma unroll
                for (int b = 0; b < 8; ++b) acc[b] += __shfl_down_sync(0xffffffffu, acc[b], off);
            if (lane == 0) {
                float bv = fb1[n];
                #pragma unroll
                for (int b = 0; b < 8; ++b) h1[b * 2048 + n] = geluf(acc[b] + bv);
            }
        }
        gsync();

        // ---- S5: FFN2 + residual -> tmp2 (blocks 0..127) ----
        if (bid < 128) {
            float acc[8];
            #pragma unroll
            for (int b = 0; b < 8; ++b) acc[b] = 0.f;
            int n = n0;   // < 1024
            for (int kk = 0; kk < 2048; kk += 1024) {
                const float4* h4 = reinterpret_cast<const float4*>(h1);
                for (int idx = tid; idx < 2048; idx += 256) {
                    int b = idx >> 8, k4i = idx & 255;
                    reinterpret_cast<float4*>(sA)[idx] =
                        __ldcg(h4 + b * 512 + (kk >> 2) + k4i);
                }
                __syncthreads();
                const float4* wr = reinterpret_cast<const float4*>(fw2 + LL n * 2048 + kk);
                for (int k4 = lane; k4 < 256; k4 += 32) {
                    float4 wv = wr[k4];
                    #pragma unroll
                    for (int b = 0; b < 8; ++b) {
                        float4 av = reinterpret_cast<const float4*>(sA + b * 1024)[k4];
                        acc[b] += wv.x * av.x + wv.y * av.y + wv.z * av.z + wv.w * av.w;
                    }
                }
                __syncthreads();
            }
            #pragma unroll
            for (int off = 16; off; off >>= 1)
                #pragma unroll
                for (int b = 0; b < 8; ++b) acc[b] += __shfl_down_sync(0xffffffffu, acc[b], off);
            if (lane == 0) {
                float bv = fb2[n];
                #pragma unroll
                for (int b = 0; b < 8; ++b)
                    tmp2[b * 1024 + n] = acc[b] + bv + resv[b];
            }
        }
        gsync();
    }
}

// Standalone LN of 8 rows (final step's LN2 -> buf slot 31).
__global__ void ln8(const float* __restrict__ x, const float* __restrict__ gg,
                    const float* __restrict__ bb, float* __restrict__ out,
                    float* __restrict__ buf, int slot)
{
    int b = blockIdx.x, tid = threadIdx.x;
    __shared__ float red[256];
    const float* xr = x + b * 1024;
    float vals[4]; float s = 0.f;
    #pragma unroll
    for (int i = 0; i < 4; ++i) { vals[i] = xr[tid + 256 * i]; s += vals[i]; }
    red[tid] = s; __syncthreads();
    for (int o = 128; o; o >>= 1) { if (tid < o) red[tid] += red[tid + o]; __syncthreads(); }
    float mean = red[0] * (1.0f / 1024.0f);
    __syncthreads();
    float v = 0.f;
    #pragma unroll
    for (int i = 0; i < 4; ++i) { float dd = vals[i] - mean; v += dd * dd; }
    red[tid] = v; __syncthreads();
    for (int o = 128; o; o >>= 1) { if (tid < o) red[tid] += red[tid + o]; __syncthreads(); }
    float inv = rsqrtf(red[0] * (1.0f / 1024.0f) + 1e-5f);
    #pragma unroll
    for (int i = 0; i < 4; ++i) {
        int d = tid + 256 * i;
        float y = (vals[i] - mean) * inv * gg[d] + bb[d];
        out[b * 1024 + d] = y;
        if (buf) buf[LL(b * 32 + slot) * 1024 + d] = y;
    }
}

// cond[l] = LN(hidden[l] + att[l])
__global__ void ln_big(const float* __restrict__ hidden, const float* __restrict__ att,
                       const float* __restrict__ gg, const float* __restrict__ bb,
                       float* __restrict__ out)
{
    int l = blockIdx.x, tid = threadIdx.x;
    __shared__ float red[256];
    const float* hr = hidden + LL l * 1024;
    const float* ar = att + LL l * 1024;
    float vals[4]; float s = 0.f;
    #pragma unroll
    for (int i = 0; i < 4; ++i) { vals[i] = hr[tid + 256 * i] + ar[tid + 256 * i]; s += vals[i]; }
    red[tid] = s; __syncthreads();
    for (int o = 128; o; o >>= 1) { if (tid < o) red[tid] += red[tid + o]; __syncthreads(); }
    float mean = red[0] * (1.0f / 1024.0f);
    __syncthreads();
    float v = 0.f;
    #pragma unroll
    for (int i = 0; i < 4; ++i) { float dd = vals[i] - mean; v += dd * dd; }
    red[tid] = v; __syncthreads();
    for (int o = 128; o; o >>= 1) { if (tid < o) red[tid] += red[tid + o]; __syncthreads(); }
    float inv = rsqrtf(red[0] * (1.0f / 1024.0f) + 1e-5f);
    #pragma unroll
    for (int i = 0; i < 4; ++i) {
        int d = tid + 256 * i;
        out[LL l * 1024 + d] = (vals[i] - mean) * inv * gg[d] + bb[d];
    }
}

// ssum[b,c,:] = softmax_s(comp_q[c].thoughts[b,s] / 32) @ thoughts[b]
__global__ __launch_bounds__(256) void comp_kernel(
    const float* __restrict__ comp_q, const float* __restrict__ thoughts,
    float* __restrict__ ssum)
{
    int b = blockIdx.x >> 3, c = blockIdx.x & 7;
    __shared__ float sc[32];
    __shared__ float pr[32];
    int tid = threadIdx.x, lane = tid & 31, w = tid >> 5;
    const float* qr = comp_q + c * 1024;
    #pragma unroll
    for (int si = 0; si < 4; ++si) {
        int s = w * 4 + si;
        const float* t = thoughts + LL(b * 32 + s) * 1024;
        float acc = 0.f;
        for (int k = lane; k < 1024; k += 32) acc += qr[k] * t[k];
        #pragma unroll
        for (int o = 16; o; o >>= 1) acc += __shfl_down_sync(0xffffffffu, acc, o);
        if (lane == 0) sc[s] = acc * (1.0f / 32.0f);
    }
    __syncthreads();
    if (tid == 0) {
        float m = -1e30f;
        for (int s = 0; s < 32; ++s) m = fmaxf(m, sc[s]);
        float S = 0.f;
        for (int s = 0; s < 32; ++s) { float p = __expf(sc[s] - m); pr[s] = p; S += p; }
        float iv = 1.0f / S;
        for (int s = 0; s < 32; ++s) pr[s] *= iv;
    }
    __syncthreads();
    for (int d = tid; d < 1024; d += 256) {
        float acc = 0.f;
        #pragma unroll
        for (int s = 0; s < 32; ++s) acc += pr[s] * thoughts[LL(b * 32 + s) * 1024 + d];
        ssum[LL(b * 8 + c) * 1024 + d] = acc;
    }
}

// Final MHA: one warp per (row l, head h); 8 keys from kvs (k|v rows).
__global__ __launch_bounds__(256) void final_attn(
    const float* __restrict__ qkvh, const float* __restrict__ kvs,
    float* __restrict__ o)
{
    int tid = threadIdx.x, lane = tid & 31, w = tid >> 5;
    int pair = blockIdx.x * 8 + w;
    int l = pair >> 4, h = pair & 15;
    int b = l >> 10;
    float2 qv = reinterpret_cast<const float2*>(qkvh + LL l * 3072 + h * 64)[lane];
    float s[8];
    #pragma unroll
    for (int ks = 0; ks < 8; ++ks) {
        float2 kv = reinterpret_cast<const float2*>(kvs + LL(b * 8 + ks) * 2048 + h * 64)[lane];
        float p = qv.x * kv.x + qv.y * kv.y;
        #pragma unroll
        for (int off = 16; off; off >>= 1) p += __shfl_xor_sync(0xffffffffu, p, off);
        s[ks] = p * 0.125f;
    }
    float m = s[0];
    #pragma unroll
    for (int ks = 1; ks < 8; ++ks) m = fmaxf(m, s[ks]);
    float sum = 0.f;
    #pragma unroll
    for (int ks = 0; ks < 8; ++ks) { s[ks] = __expf(s[ks] - m); sum += s[ks]; }
    float inv = 1.0f / sum;
    float o0 = 0.f, o1 = 0.f;
    #pragma unroll
    for (int ks = 0; ks < 8; ++ks) {
        float2 vv = reinterpret_cast<const float2*>(kvs + LL(b * 8 + ks) * 2048 + 1024 + h * 64)[lane];
        o0 += s[ks] * vv.x; o1 += s[ks] * vv.y;
    }
    float2 ov; ov.x = o0 * inv; ov.y = o1 * inv;
    reinterpret_cast<float2*>(o + LL l * 1024 + h * 64)[lane] = ov;
}

extern "C" void kernel_launch(void* const* d_in, const int* in_sizes, int n_in,
                              void* d_out, int out_size) {
    (void)in_sizes; (void)n_in; (void)out_size;
    const float* hidden = (const float*)d_in[0];
    const float* tpw    = (const float*)d_in[1];
    const float* tpb    = (const float*)d_in[2];
    const float* ln1g   = (const float*)d_in[3];
    const float* ln1b   = (const float*)d_in[4];
    const float* ln2g   = (const float*)d_in[5];
    const float* ln2b   = (const float*)d_in[6];
    const float* aiw    = (const float*)d_in[7];
    const float* aib    = (const float*)d_in[8];
    const float* aow    = (const float*)d_in[9];
    const float* aob    = (const float*)d_in[10];
    const float* fw1    = (const float*)d_in[11];
    const float* fb1    = (const float*)d_in[12];
    const float* fw2    = (const float*)d_in[13];
    const float* fb2    = (const float*)d_in[14];
    const float* cq     = (const float*)d_in[15];
    const float* cw     = (const float*)d_in[16];
    const float* cb     = (const float*)d_in[17];
    float* out = (float*)d_out;

    float* S;
    cudaGetSymbolAddress((void**)&S, g_scratch);
    float* QKVH = S + OFF_QKVH;
    float* BUF  = S + OFF_BUF;
    float* KVB  = S + OFF_KVB;
    float* CTX  = S + OFF_CTX;
    float* TOK  = S + OFF_TOK;
    float* TMP  = S + OFF_TMP;
    float* TMP2 = S + OFF_TMP2;
    float* H1   = S + OFF_H1;
    float* Q    = S + OFF_Q;
    float* AO   = S + OFF_AO;
    float* KVS  = S + OFF_KVS;
    float* SSUM = S + OFF_SSUM;
    float* O    = S + OFF_O;
    float* ATT  = S + OFF_ATT;
    float* SUMM = out + LL 8192 * 1024;   // (8,8,1024) tail of output

    // Phase A
    mean_kernel<<<dim3(4, 8), 256>>>(hidden, CTX);
    smallgemm8<<<128, 256>>>(CTX, 1024, tpw, tpb, TOK, 1024);
    copy_to_buf<<<dim3(8, 4), 256>>>(TOK, BUF, 0);
    sgemm<<<dim3(48, 64), 256>>>(hidden, aiw, aib, QKVH, 8192, 3072, 1024);

    // Phase B: entire 31-step recurrence in one persistent kernel (256 blocks)
    loop_kernel<<<256, 256>>>(aiw, aib, aow, aob, fw1, fb1, fw2, fb2,
                              ln1g, ln1b, ln2g, ln2b, QKVH, TOK,
                              Q, KVB, AO, TMP, H1, TMP2, BUF);
    // Final LN2 -> buf[:,31]
    ln8<<<8, 256>>>(TMP2, ln2g, ln2b, TOK, BUF, 31);

    // Phase C
    comp_kernel<<<64, 256>>>(cq, BUF, SSUM);
    sgemm<<<dim3(16, 1), 256>>>(SSUM, cw, cb, SUMM, 64, 1024, 1024);
    sgemm<<<dim3(32, 1), 256>>>(SUMM, aiw + LL 1024 * 1024, aib + 1024, KVS, 64, 2048, 1024);
    final_attn<<<16384, 256>>>(QKVH, KVS, O);
    sgemm<<<dim3(16, 64), 256>>>(O, aow, aob, ATT, 8192, 1024, 1024);
    ln_big<<<8192, 256>>>(hidden, ATT, ln1g, ln1b, out);
}